// round 1
// baseline (speedup 1.0000x reference)
#include <cuda_runtime.h>
#include <cstdint>

// Problem constants (registry shapes)
#define MAX_LOCAL 55000
#define C1 128
#define C2 64

// Scratch (static device globals: allocation-free, zero-initialized at load)
__device__ float g_h   [MAX_LOCAL * C1];   // (X W1) * deg
__device__ float g_agg [MAX_LOCAL * C1];   // scatter accumulator layer 1
__device__ float g_x2  [MAX_LOCAL * C1];   // padded relu output (tail rows stay 0)
__device__ float g_h2  [MAX_LOCAL * C2];   // (X2 W2) * deg
__device__ float g_agg2[MAX_LOCAL * C2];   // scatter accumulator layer 2

// ---------------------------------------------------------------------------
// GEMM: out[r, :] = (X[r, :] @ W) * deg[r],  K = 128 fixed, N = 128 or 64
// Block: 64 rows x N cols, 256 threads. K chunked by 32.
// ---------------------------------------------------------------------------
template<int N>
__global__ __launch_bounds__(256) void gemm_deg(
    const float* __restrict__ X, const float* __restrict__ W,
    const float* __restrict__ deg, float* __restrict__ out, int rows)
{
    constexpr int BM = 64, BK = 32, K = 128;
    constexpr int NC = N / 4;       // col groups (32 or 16)
    constexpr int RG = 256 / NC;    // row groups (8 or 16)
    constexpr int TM = BM / RG;     // rows per thread (8 or 4)

    __shared__ float xs[BK][BM + 4];   // transposed x tile, padded (keeps 16B align)
    __shared__ float ws[BK][N];

    const int t     = threadIdx.x;
    const int rbase = blockIdx.x * BM;
    const int cg    = t % NC;
    const int rg    = t / NC;

    float acc[TM][4];
#pragma unroll
    for (int m = 0; m < TM; ++m) { acc[m][0]=0.f; acc[m][1]=0.f; acc[m][2]=0.f; acc[m][3]=0.f; }

    for (int kb = 0; kb < K; kb += BK) {
        // ---- load X tile (transposed into shared) ----
        {
            const int c8 = t % 8;       // float4 index along K (8 per 32-k chunk)
            const int r0 = t / 8;       // 32 rows per pass
#pragma unroll
            for (int it = 0; it < 2; ++it) {
                const int r  = r0 + it * 32;
                const int gr = rbase + r;
                float4 v = make_float4(0.f, 0.f, 0.f, 0.f);
                if (gr < rows)
                    v = *(const float4*)(X + (size_t)gr * K + kb + c8 * 4);
                xs[c8 * 4 + 0][r] = v.x;
                xs[c8 * 4 + 1][r] = v.y;
                xs[c8 * 4 + 2][r] = v.z;
                xs[c8 * 4 + 3][r] = v.w;
            }
        }
        // ---- load W tile ----
#pragma unroll
        for (int i = t; i < BK * N / 4; i += 256) {
            const int kk = i / (N / 4);
            const int c  = i % (N / 4);
            *(float4*)&ws[kk][c * 4] =
                *(const float4*)(W + (size_t)(kb + kk) * N + c * 4);
        }
        __syncthreads();

#pragma unroll
        for (int kk = 0; kk < BK; ++kk) {
            const float4 wv = *(const float4*)&ws[kk][cg * 4];
            float xr[TM];
#pragma unroll
            for (int m = 0; m < TM; m += 4) {
                const float4 xv = *(const float4*)&xs[kk][rg * TM + m];
                xr[m+0] = xv.x; xr[m+1] = xv.y; xr[m+2] = xv.z; xr[m+3] = xv.w;
            }
#pragma unroll
            for (int m = 0; m < TM; ++m) {
                acc[m][0] = fmaf(xr[m], wv.x, acc[m][0]);
                acc[m][1] = fmaf(xr[m], wv.y, acc[m][1]);
                acc[m][2] = fmaf(xr[m], wv.z, acc[m][2]);
                acc[m][3] = fmaf(xr[m], wv.w, acc[m][3]);
            }
        }
        __syncthreads();
    }

#pragma unroll
    for (int m = 0; m < TM; ++m) {
        const int gr = rbase + rg * TM + m;
        if (gr < rows) {
            const float d = deg[gr];
            float4 o;
            o.x = acc[m][0] * d; o.y = acc[m][1] * d;
            o.z = acc[m][2] * d; o.w = acc[m][3] * d;
            *(float4*)(out + (size_t)gr * N + cg * 4) = o;
        }
    }
}

// ---------------------------------------------------------------------------
// Scatter-add: agg[er[e], :] += H[ec[e], :]   (C/4 threads per edge, float4,
// vectorized global reduction — no return value, L2-side accumulation)
// ---------------------------------------------------------------------------
template<int C>
__global__ __launch_bounds__(256) void scatter_add(
    const float* __restrict__ H, const int* __restrict__ er,
    const int* __restrict__ ec, float* __restrict__ A, int nE)
{
    constexpr int G = C / 4;
    const long long tid = (long long)blockIdx.x * blockDim.x + threadIdx.x;
    const int e  = (int)(tid / G);
    const int li = (int)(tid % G);
    if (e >= nE) return;
    const int r = __ldg(er + e);
    const int c = __ldg(ec + e);
    const float4 v = *(const float4*)(H + (size_t)c * C + li * 4);
    float* dst = A + (size_t)r * C + li * 4;
    asm volatile("red.global.add.v4.f32 [%0], {%1,%2,%3,%4};"
                 :: "l"(dst), "f"(v.x), "f"(v.y), "f"(v.z), "f"(v.w)
                 : "memory");
}

// ---------------------------------------------------------------------------
// x2[:owned] = relu(agg * deg[row] + b1)   (float4 granularity, C1 = 128)
// ---------------------------------------------------------------------------
__global__ __launch_bounds__(256) void relu_bias_pad(
    const float* __restrict__ agg, const float* __restrict__ deg,
    const float* __restrict__ b, float* __restrict__ x2, int owned)
{
    const int i = blockIdx.x * blockDim.x + threadIdx.x;
    const int n4 = owned * (C1 / 4);
    if (i >= n4) return;
    const int row = i >> 5;           // C1/4 = 32
    const int c   = i & 31;
    const float d = __ldg(deg + row);
    const float4 a  = ((const float4*)agg)[i];
    const float4 bb = ((const float4*)b)[c];
    float4 o;
    o.x = fmaxf(fmaf(a.x, d, bb.x), 0.f);
    o.y = fmaxf(fmaf(a.y, d, bb.y), 0.f);
    o.z = fmaxf(fmaf(a.z, d, bb.z), 0.f);
    o.w = fmaxf(fmaf(a.w, d, bb.w), 0.f);
    ((float4*)x2)[i] = o;
}

// out[:owned] = agg2 * deg[row] + b2    (C2 = 64)
__global__ __launch_bounds__(256) void out_bias(
    const float* __restrict__ agg, const float* __restrict__ deg,
    const float* __restrict__ b, float* __restrict__ out, int owned)
{
    const int i = blockIdx.x * blockDim.x + threadIdx.x;
    const int n4 = owned * (C2 / 4);
    if (i >= n4) return;
    const int row = i >> 4;           // C2/4 = 16
    const int c   = i & 15;
    const float d = __ldg(deg + row);
    const float4 a  = ((const float4*)agg)[i];
    const float4 bb = ((const float4*)b)[c];
    float4 o;
    o.x = fmaf(a.x, d, bb.x);
    o.y = fmaf(a.y, d, bb.y);
    o.z = fmaf(a.z, d, bb.z);
    o.w = fmaf(a.w, d, bb.w);
    ((float4*)out)[i] = o;
}

// ---------------------------------------------------------------------------
extern "C" void kernel_launch(void* const* d_in, const int* in_sizes, int n_in,
                              void* d_out, int out_size)
{
    const float* x   = (const float*)d_in[0];
    const float* deg = (const float*)d_in[1];
    const float* w1  = (const float*)d_in[2];
    const float* b1  = (const float*)d_in[3];
    const float* w2  = (const float*)d_in[4];
    const float* b2  = (const float*)d_in[5];
    const int*   er  = (const int*)d_in[6];
    const int*   ec  = (const int*)d_in[7];

    const int nloc  = in_sizes[0] / C1;     // 55000
    const int nE    = in_sizes[6];          // 800000
    const int owned = out_size / C2;        // 50000
    float* out = (float*)d_out;

    float *p_h, *p_agg, *p_x2, *p_h2, *p_agg2;
    cudaGetSymbolAddress((void**)&p_h,    g_h);
    cudaGetSymbolAddress((void**)&p_agg,  g_agg);
    cudaGetSymbolAddress((void**)&p_x2,   g_x2);
    cudaGetSymbolAddress((void**)&p_h2,   g_h2);
    cudaGetSymbolAddress((void**)&p_agg2, g_agg2);

    // zero accumulators (+ halo tail of x2, written nowhere else) every call
    cudaMemsetAsync(p_agg,  0, (size_t)nloc * C1 * sizeof(float), 0);
    cudaMemsetAsync(p_agg2, 0, (size_t)nloc * C2 * sizeof(float), 0);
    cudaMemsetAsync(p_x2 + (size_t)owned * C1, 0,
                    (size_t)(nloc - owned) * C1 * sizeof(float), 0);

    // Layer 1
    gemm_deg<C1><<<(nloc + 63) / 64, 256>>>(x, w1, deg, p_h, nloc);
    {
        const long long th = (long long)nE * (C1 / 4);
        scatter_add<C1><<<(unsigned)((th + 255) / 256), 256>>>(p_h, er, ec, p_agg, nE);
    }
    relu_bias_pad<<<(owned * (C1 / 4) + 255) / 256, 256>>>(p_agg, deg, b1, p_x2, owned);

    // Layer 2
    gemm_deg<C2><<<(nloc + 63) / 64, 256>>>(p_x2, w2, deg, p_h2, nloc);
    {
        const long long th = (long long)nE * (C2 / 4);
        scatter_add<C2><<<(unsigned)((th + 255) / 256), 256>>>(p_h2, er, ec, p_agg2, nE);
    }
    out_bias<<<(owned * (C2 / 4) + 255) / 256, 256>>>(p_agg2, deg, b2, out, owned);
}

// round 2
// speedup vs baseline: 1.6263x; 1.6263x over previous
#include <cuda_runtime.h>
#include <cstdint>

#define MAX_LOCAL 55000
#define MAX_EDGES 800000
#define C1 128
#define C2 64

// ---- static scratch (allocation-free) ----
__device__ float g_h   [MAX_LOCAL * C1];     // (X W1) * deg
__device__ float g_x2  [MAX_LOCAL * C1];     // relu output (only owned rows used)
__device__ float g_h2  [MAX_LOCAL * C2];     // (X2 W2) * deg (only owned rows used)
__device__ int   g_rowstart[MAX_LOCAL + 1];  // CSR row offsets (also histogram buf)
__device__ int   g_cursor  [MAX_LOCAL];      // fill cursors
__device__ int   g_csrcol  [MAX_EDGES];      // CSR column indices
__device__ int   g_bsum    [256];            // scan block sums

// ===========================================================================
// CSR build: histogram -> 3-phase exclusive scan -> fill
// ===========================================================================
__global__ __launch_bounds__(256) void edge_hist(
    const int* __restrict__ er, int* __restrict__ cnt, int nE)
{
    int e = blockIdx.x * blockDim.x + threadIdx.x;
    if (e < nE) atomicAdd(&cnt[er[e]], 1);
}

// per-1024-chunk exclusive scan; blockDim=256, 4 elems/thread
__global__ __launch_bounds__(256) void scan_blocks(
    const int* __restrict__ cnt, int* __restrict__ excl,
    int* __restrict__ bsum, int n)
{
    __shared__ int wsum[8];
    const int base = blockIdx.x * 1024 + threadIdx.x * 4;
    int v[4]; int s = 0;
#pragma unroll
    for (int k = 0; k < 4; ++k) {
        int idx = base + k;
        v[k] = (idx < n) ? cnt[idx] : 0;
        s += v[k];
    }
    const int lane = threadIdx.x & 31, wid = threadIdx.x >> 5;
    int incl = s;
#pragma unroll
    for (int o = 1; o < 32; o <<= 1) {
        int t = __shfl_up_sync(~0u, incl, o);
        if (lane >= o) incl += t;
    }
    if (lane == 31) wsum[wid] = incl;
    __syncthreads();
    if (wid == 0) {
        int ws = (lane < 8) ? wsum[lane] : 0;
#pragma unroll
        for (int o = 1; o < 8; o <<= 1) {
            int t = __shfl_up_sync(~0u, ws, o);
            if (lane >= o) ws += t;
        }
        if (lane < 8) wsum[lane] = ws;
    }
    __syncthreads();
    int run = incl - s + (wid ? wsum[wid - 1] : 0);
#pragma unroll
    for (int k = 0; k < 4; ++k) {
        int idx = base + k;
        if (idx < n) excl[idx] = run;
        run += v[k];
    }
    if (threadIdx.x == 255) bsum[blockIdx.x] = wsum[7];
}

// exclusive scan of <=256 block sums, single block
__global__ __launch_bounds__(256) void scan_small(int* bsum, int nB)
{
    __shared__ int sh[256];
    const int t = threadIdx.x;
    int v = (t < nB) ? bsum[t] : 0;
    sh[t] = v;
    __syncthreads();
    for (int o = 1; o < 256; o <<= 1) {
        int add = (t >= o) ? sh[t - o] : 0;
        __syncthreads();
        sh[t] += add;
        __syncthreads();
    }
    if (t < nB) bsum[t] = sh[t] - v;   // exclusive
}

__global__ __launch_bounds__(256) void add_offsets(
    int* __restrict__ excl, const int* __restrict__ bsum, int n, int nE)
{
    int idx = blockIdx.x * blockDim.x + threadIdx.x;
    if (idx < n) excl[idx] += bsum[idx >> 10];
    if (idx == 0) excl[n] = nE;
}

__global__ __launch_bounds__(256) void csr_fill(
    const int* __restrict__ er, const int* __restrict__ ec,
    int* __restrict__ cursor, int* __restrict__ col, int nE)
{
    int e = blockIdx.x * blockDim.x + threadIdx.x;
    if (e < nE) {
        int p = atomicAdd(&cursor[er[e]], 1);
        col[p] = ec[e];
    }
}

// ===========================================================================
// GEMM: out[r,:] = (X[r,:] @ W) * deg[r],  K=128, N in {128,64}
// ===========================================================================
template<int N>
__global__ __launch_bounds__(256) void gemm_deg(
    const float* __restrict__ X, const float* __restrict__ W,
    const float* __restrict__ deg, float* __restrict__ out, int rows)
{
    constexpr int BM = 64, BK = 32, K = 128;
    constexpr int NC = N / 4;
    constexpr int RG = 256 / NC;
    constexpr int TM = BM / RG;

    __shared__ float xs[BK][BM + 4];
    __shared__ float ws[BK][N];

    const int t     = threadIdx.x;
    const int rbase = blockIdx.x * BM;
    const int cg    = t % NC;
    const int rg    = t / NC;

    float acc[TM][4];
#pragma unroll
    for (int m = 0; m < TM; ++m) { acc[m][0]=0.f; acc[m][1]=0.f; acc[m][2]=0.f; acc[m][3]=0.f; }

    for (int kb = 0; kb < K; kb += BK) {
        {
            const int c8 = t % 8;
            const int r0 = t / 8;
#pragma unroll
            for (int it = 0; it < 2; ++it) {
                const int r  = r0 + it * 32;
                const int gr = rbase + r;
                float4 v = make_float4(0.f, 0.f, 0.f, 0.f);
                if (gr < rows)
                    v = *(const float4*)(X + (size_t)gr * K + kb + c8 * 4);
                xs[c8 * 4 + 0][r] = v.x;
                xs[c8 * 4 + 1][r] = v.y;
                xs[c8 * 4 + 2][r] = v.z;
                xs[c8 * 4 + 3][r] = v.w;
            }
        }
#pragma unroll
        for (int i = t; i < BK * N / 4; i += 256) {
            const int kk = i / (N / 4);
            const int c  = i % (N / 4);
            *(float4*)&ws[kk][c * 4] =
                *(const float4*)(W + (size_t)(kb + kk) * N + c * 4);
        }
        __syncthreads();

#pragma unroll
        for (int kk = 0; kk < BK; ++kk) {
            const float4 wv = *(const float4*)&ws[kk][cg * 4];
            float xr[TM];
#pragma unroll
            for (int m = 0; m < TM; m += 4) {
                const float4 xv = *(const float4*)&xs[kk][rg * TM + m];
                xr[m+0] = xv.x; xr[m+1] = xv.y; xr[m+2] = xv.z; xr[m+3] = xv.w;
            }
#pragma unroll
            for (int m = 0; m < TM; ++m) {
                acc[m][0] = fmaf(xr[m], wv.x, acc[m][0]);
                acc[m][1] = fmaf(xr[m], wv.y, acc[m][1]);
                acc[m][2] = fmaf(xr[m], wv.z, acc[m][2]);
                acc[m][3] = fmaf(xr[m], wv.w, acc[m][3]);
            }
        }
        __syncthreads();
    }

#pragma unroll
    for (int m = 0; m < TM; ++m) {
        const int gr = rbase + rg * TM + m;
        if (gr < rows) {
            const float d = deg[gr];
            float4 o;
            o.x = acc[m][0] * d; o.y = acc[m][1] * d;
            o.z = acc[m][2] * d; o.w = acc[m][3] * d;
            *(float4*)(out + (size_t)gr * N + cg * 4) = o;
        }
    }
}

// ===========================================================================
// Gather layer 1: x2[row,:] = relu( (sum_j h[col_j,:]) * deg[row] + b1 )
// one warp per owned row, float4 lanes (C1=128)
// ===========================================================================
__global__ __launch_bounds__(256) void gather_relu(
    const float* __restrict__ H, const int* __restrict__ rs,
    const int* __restrict__ cols, const float* __restrict__ deg,
    const float* __restrict__ b, float* __restrict__ x2, int owned)
{
    const int row  = (blockIdx.x * 256 + threadIdx.x) >> 5;
    const int lane = threadIdx.x & 31;
    if (row >= owned) return;
    const int s = __ldg(rs + row);
    const int e = __ldg(rs + row + 1);

    float4 a0 = make_float4(0.f, 0.f, 0.f, 0.f);
    float4 a1 = make_float4(0.f, 0.f, 0.f, 0.f);
    int j = s;
    for (; j + 1 < e; j += 2) {
        const int c0 = __ldg(cols + j);
        const int c1 = __ldg(cols + j + 1);
        const float4 v0 = *(const float4*)(H + (size_t)c0 * C1 + lane * 4);
        const float4 v1 = *(const float4*)(H + (size_t)c1 * C1 + lane * 4);
        a0.x += v0.x; a0.y += v0.y; a0.z += v0.z; a0.w += v0.w;
        a1.x += v1.x; a1.y += v1.y; a1.z += v1.z; a1.w += v1.w;
    }
    if (j < e) {
        const int c0 = __ldg(cols + j);
        const float4 v0 = *(const float4*)(H + (size_t)c0 * C1 + lane * 4);
        a0.x += v0.x; a0.y += v0.y; a0.z += v0.z; a0.w += v0.w;
    }
    const float d = __ldg(deg + row);
    const float4 bb = ((const float4*)b)[lane];
    float4 o;
    o.x = fmaxf(fmaf(a0.x + a1.x, d, bb.x), 0.f);
    o.y = fmaxf(fmaf(a0.y + a1.y, d, bb.y), 0.f);
    o.z = fmaxf(fmaf(a0.z + a1.z, d, bb.z), 0.f);
    o.w = fmaxf(fmaf(a0.w + a1.w, d, bb.w), 0.f);
    *(float4*)(x2 + (size_t)row * C1 + lane * 4) = o;
}

// ===========================================================================
// Gather layer 2: out[row,:] = (sum_{j, col_j<owned} h2[col_j,:]) * deg[row] + b2
// one warp per owned row, float2 lanes (C2=64)
// ===========================================================================
__global__ __launch_bounds__(256) void gather_out(
    const float* __restrict__ H, const int* __restrict__ rs,
    const int* __restrict__ cols, const float* __restrict__ deg,
    const float* __restrict__ b, float* __restrict__ out, int owned)
{
    const int row  = (blockIdx.x * 256 + threadIdx.x) >> 5;
    const int lane = threadIdx.x & 31;
    if (row >= owned) return;
    const int s = __ldg(rs + row);
    const int e = __ldg(rs + row + 1);

    float2 a0 = make_float2(0.f, 0.f);
    float2 a1 = make_float2(0.f, 0.f);
    int j = s;
    for (; j + 1 < e; j += 2) {
        const int c0 = __ldg(cols + j);
        const int c1 = __ldg(cols + j + 1);
        if (c0 < owned) {
            const float2 v = *(const float2*)(H + (size_t)c0 * C2 + lane * 2);
            a0.x += v.x; a0.y += v.y;
        }
        if (c1 < owned) {
            const float2 v = *(const float2*)(H + (size_t)c1 * C2 + lane * 2);
            a1.x += v.x; a1.y += v.y;
        }
    }
    if (j < e) {
        const int c0 = __ldg(cols + j);
        if (c0 < owned) {
            const float2 v = *(const float2*)(H + (size_t)c0 * C2 + lane * 2);
            a0.x += v.x; a0.y += v.y;
        }
    }
    const float d = __ldg(deg + row);
    const float2 bb = ((const float2*)b)[lane];
    float2 o;
    o.x = fmaf(a0.x + a1.x, d, bb.x);
    o.y = fmaf(a0.y + a1.y, d, bb.y);
    *(float2*)(out + (size_t)row * C2 + lane * 2) = o;
}

// ===========================================================================
extern "C" void kernel_launch(void* const* d_in, const int* in_sizes, int n_in,
                              void* d_out, int out_size)
{
    const float* x   = (const float*)d_in[0];
    const float* deg = (const float*)d_in[1];
    const float* w1  = (const float*)d_in[2];
    const float* b1  = (const float*)d_in[3];
    const float* w2  = (const float*)d_in[4];
    const float* b2  = (const float*)d_in[5];
    const int*   er  = (const int*)d_in[6];
    const int*   ec  = (const int*)d_in[7];

    const int nloc  = in_sizes[0] / C1;     // 55000
    const int nE    = in_sizes[6];          // 800000
    const int owned = out_size / C2;        // 50000
    float* out = (float*)d_out;

    float *p_h, *p_x2, *p_h2;
    int *p_rs, *p_cur, *p_col, *p_bsum;
    cudaGetSymbolAddress((void**)&p_h,    g_h);
    cudaGetSymbolAddress((void**)&p_x2,   g_x2);
    cudaGetSymbolAddress((void**)&p_h2,   g_h2);
    cudaGetSymbolAddress((void**)&p_rs,   g_rowstart);
    cudaGetSymbolAddress((void**)&p_cur,  g_cursor);
    cudaGetSymbolAddress((void**)&p_col,  g_csrcol);
    cudaGetSymbolAddress((void**)&p_bsum, g_bsum);

    // ---- CSR build ----
    cudaMemsetAsync(p_cur, 0, (size_t)nloc * sizeof(int), 0);   // reuse as hist
    edge_hist<<<(nE + 255) / 256, 256>>>(er, p_cur, nE);
    const int nB = (nloc + 1023) / 1024;
    scan_blocks<<<nB, 256>>>(p_cur, p_rs, p_bsum, nloc);
    scan_small<<<1, 256>>>(p_bsum, nB);
    add_offsets<<<(nloc + 255) / 256, 256>>>(p_rs, p_bsum, nloc, nE);
    cudaMemcpyAsync(p_cur, p_rs, (size_t)nloc * sizeof(int),
                    cudaMemcpyDeviceToDevice, 0);
    csr_fill<<<(nE + 255) / 256, 256>>>(er, ec, p_cur, p_col, nE);

    // ---- Layer 1 ----
    gemm_deg<C1><<<(nloc + 63) / 64, 256>>>(x, w1, deg, p_h, nloc);
    gather_relu<<<(owned * 32 + 255) / 256, 256>>>(p_h, p_rs, p_col, deg, b1, p_x2, owned);

    // ---- Layer 2 (only owned rows matter anywhere) ----
    gemm_deg<C2><<<(owned + 63) / 64, 256>>>(p_x2, w2, deg, p_h2, owned);
    gather_out<<<(owned * 32 + 255) / 256, 256>>>(p_h2, p_rs, p_col, deg, b2, out, owned);
}

// round 4
// speedup vs baseline: 1.8313x; 1.1260x over previous
#include <cuda_runtime.h>
#include <cstdint>

#define MAX_LOCAL 55000
#define MAX_EDGES 800000
#define C1 128
#define C2 64

// ---- static scratch (allocation-free) ----
__device__ float g_h   [MAX_LOCAL * C1];     // (X W1) * deg
__device__ float g_x2  [MAX_LOCAL * C1];     // relu output (owned rows only)
__device__ float g_h2  [MAX_LOCAL * C2];     // (X2 W2) * deg (owned rows only)
__device__ int   g_rowstart[MAX_LOCAL + 1];  // CSR row offsets
__device__ int   g_cursor  [MAX_LOCAL];      // fill cursors
__device__ int   g_csrcol  [MAX_EDGES];      // CSR column indices
// meta: [0, MAX_LOCAL) histogram | [MAX_LOCAL, +64) lookback flags
//       [+64, +128) block aggregates | [+128, +192) block prefixes
__device__ int   g_meta[MAX_LOCAL + 192];

// ===========================================================================
// CSR build
// ===========================================================================
__global__ __launch_bounds__(256) void edge_hist(
    const int* __restrict__ er, int* __restrict__ cnt, int nE)
{
    int e = blockIdx.x * blockDim.x + threadIdx.x;
    if (e < nE) atomicAdd(&cnt[er[e]], 1);
}

// single-pass decoupled-lookback exclusive scan; 1024 threads, 1 elem/thread.
// writes rowstart AND cursor. flags must be zeroed before launch.
__global__ __launch_bounds__(1024) void scan_csr(
    const int* __restrict__ cnt, int* __restrict__ rs, int* __restrict__ cur,
    int* flags, int* agg, int* pfx, int n)
{
    __shared__ int wsum[32];
    __shared__ int s_excl;
    const int b = blockIdx.x, t = threadIdx.x;
    const int i = b * 1024 + t;
    const int lane = t & 31, wid = t >> 5;

    int v = (i < n) ? cnt[i] : 0;
    int incl = v;
#pragma unroll
    for (int o = 1; o < 32; o <<= 1) {
        int u = __shfl_up_sync(~0u, incl, o);
        if (lane >= o) incl += u;
    }
    if (lane == 31) wsum[wid] = incl;
    __syncthreads();
    if (wid == 0) {
        int ws = wsum[lane];
#pragma unroll
        for (int o = 1; o < 32; o <<= 1) {
            int u = __shfl_up_sync(~0u, ws, o);
            if (lane >= o) ws += u;
        }
        wsum[lane] = ws;
    }
    __syncthreads();
    const int blockIncl = incl + (wid ? wsum[wid - 1] : 0);
    const int total = wsum[31];

    if (t == 0) {
        agg[b] = total;
        __threadfence();
        ((volatile int*)flags)[b] = 1;
        int ex = 0;
        for (int p = b - 1; p >= 0; --p) {
            int f;
            do { f = ((volatile int*)flags)[p]; } while (f == 0);
            __threadfence();
            if (f == 2) { ex += pfx[p]; break; }
            ex += agg[p];
        }
        pfx[b] = ex + total;
        __threadfence();
        ((volatile int*)flags)[b] = 2;
        s_excl = ex;
    }
    __syncthreads();
    if (i < n) {
        const int base = s_excl + blockIncl - v;  // exclusive
        rs[i]  = base;
        cur[i] = base;
    }
}

__global__ __launch_bounds__(256) void csr_fill(
    const int* __restrict__ er, const int* __restrict__ ec,
    int* __restrict__ cursor, int* __restrict__ col, int nE)
{
    int e = blockIdx.x * blockDim.x + threadIdx.x;
    if (e < nE) {
        int p = atomicAdd(&cursor[er[e]], 1);
        col[p] = ec[e];
    }
}

// ===========================================================================
// TF32 tensor-core GEMM: out[r, nb:nb+64] = (X[r,:K=128] @ W[:,nb:nb+64])*deg[r]
// Block 256 thr = 8 warps (4 m x 2 n). BM=128, BN=64, K chunked by 32.
// n_ld = row stride of W and out (128 for layer1, 64 for layer2).
// ===========================================================================
__device__ __forceinline__ unsigned f2tf(float f) {
    unsigned u;
    asm("cvt.rna.tf32.f32 %0, %1;" : "=r"(u) : "f"(f));
    return u;
}

__global__ __launch_bounds__(256) void gemm_tf32(
    const float* __restrict__ X, const float* __restrict__ W,
    const float* __restrict__ deg, float* __restrict__ out,
    int rows, int n_ld)
{
    constexpr int K = 128, BK = 32, BM = 128;
    constexpr int XS = BM + 8;   // 136: conflict-free A-frag LDS
    constexpr int WS = 64 + 8;   // 72:  conflict-free B-frag LDS
    __shared__ unsigned xs[BK][XS];
    __shared__ unsigned ws[BK][WS];

    const int t     = threadIdx.x;
    const int warp  = t >> 5;
    const int lane  = t & 31;
    const int gID   = lane >> 2;    // 0..7
    const int tig   = lane & 3;     // 0..3
    const int warpM = warp >> 1;    // 0..3 -> m offset *32
    const int warpN = warp & 1;     // 0..1 -> n offset *32
    const int rbase = blockIdx.x * BM;
    const int nbase = blockIdx.y * 64;

    float acc[2][4][4];             // [mt][nt][c]
#pragma unroll
    for (int mt = 0; mt < 2; ++mt)
#pragma unroll
        for (int nt = 0; nt < 4; ++nt)
#pragma unroll
            for (int c = 0; c < 4; ++c) acc[mt][nt][c] = 0.f;

    const int xrow = t & 127;       // loader row
    const int half = t >> 7;        // 0/1

    for (int kb = 0; kb < K; kb += BK) {
        // ---- load X tile: transposed + tf32 cvt ----
        {
            const int grow = rbase + xrow;
            const bool ok = grow < rows;
            const float4* Xp = (const float4*)(X + (size_t)grow * K + kb);
#pragma unroll
            for (int j = 0; j < 4; ++j) {
                const int k4 = half * 4 + j;
                float4 v = ok ? Xp[k4] : make_float4(0.f, 0.f, 0.f, 0.f);
                xs[k4 * 4 + 0][xrow] = f2tf(v.x);
                xs[k4 * 4 + 1][xrow] = f2tf(v.y);
                xs[k4 * 4 + 2][xrow] = f2tf(v.z);
                xs[k4 * 4 + 3][xrow] = f2tf(v.w);
            }
        }
        // ---- load W tile ----
#pragma unroll
        for (int it = 0; it < 2; ++it) {
            const int idx = t + it * 256;
            const int n4  = idx & 15;
            const int kk  = idx >> 4;
            const float4 v = *(const float4*)(W + (size_t)(kb + kk) * n_ld + nbase + n4 * 4);
            ws[kk][n4 * 4 + 0] = f2tf(v.x);
            ws[kk][n4 * 4 + 1] = f2tf(v.y);
            ws[kk][n4 * 4 + 2] = f2tf(v.z);
            ws[kk][n4 * 4 + 3] = f2tf(v.w);
        }
        __syncthreads();

#pragma unroll
        for (int step = 0; step < BK / 8; ++step) {
            const int k0 = step * 8;
            unsigned a[2][4], bfr[4][2];
#pragma unroll
            for (int mt = 0; mt < 2; ++mt) {
                const int m0 = warpM * 32 + mt * 16 + gID;
                a[mt][0] = xs[k0 + tig    ][m0];
                a[mt][1] = xs[k0 + tig    ][m0 + 8];
                a[mt][2] = xs[k0 + tig + 4][m0];
                a[mt][3] = xs[k0 + tig + 4][m0 + 8];
            }
#pragma unroll
            for (int nt = 0; nt < 4; ++nt) {
                const int n0 = warpN * 32 + nt * 8 + gID;
                bfr[nt][0] = ws[k0 + tig    ][n0];
                bfr[nt][1] = ws[k0 + tig + 4][n0];
            }
#pragma unroll
            for (int mt = 0; mt < 2; ++mt)
#pragma unroll
                for (int nt = 0; nt < 4; ++nt) {
                    asm volatile(
                        "mma.sync.aligned.m16n8k8.row.col.f32.tf32.tf32.f32 "
                        "{%0,%1,%2,%3}, {%4,%5,%6,%7}, {%8,%9}, {%0,%1,%2,%3};"
                        : "+f"(acc[mt][nt][0]), "+f"(acc[mt][nt][1]),
                          "+f"(acc[mt][nt][2]), "+f"(acc[mt][nt][3])
                        : "r"(a[mt][0]), "r"(a[mt][1]), "r"(a[mt][2]), "r"(a[mt][3]),
                          "r"(bfr[nt][0]), "r"(bfr[nt][1]));
                }
        }
        __syncthreads();
    }

    // ---- epilogue: *deg, store float2 pairs ----
#pragma unroll
    for (int mt = 0; mt < 2; ++mt) {
        const int r0 = rbase + warpM * 32 + mt * 16 + gID;
        const int r1 = r0 + 8;
        const float d0 = (r0 < rows) ? deg[r0] : 0.f;
        const float d1 = (r1 < rows) ? deg[r1] : 0.f;
#pragma unroll
        for (int nt = 0; nt < 4; ++nt) {
            const int cc = nbase + warpN * 32 + nt * 8 + tig * 2;
            if (r0 < rows) {
                float2 o = make_float2(acc[mt][nt][0] * d0, acc[mt][nt][1] * d0);
                *(float2*)(out + (size_t)r0 * n_ld + cc) = o;
            }
            if (r1 < rows) {
                float2 o = make_float2(acc[mt][nt][2] * d1, acc[mt][nt][3] * d1);
                *(float2*)(out + (size_t)r1 * n_ld + cc) = o;
            }
        }
    }
}

// ===========================================================================
// Gather layer 1: x2[row,:] = relu( (sum_j h[col_j,:]) * deg[row] + b1 )
// ===========================================================================
__global__ __launch_bounds__(256) void gather_relu(
    const float* __restrict__ H, const int* __restrict__ rs,
    const int* __restrict__ cols, const float* __restrict__ deg,
    const float* __restrict__ b, float* __restrict__ x2, int owned)
{
    const int row  = (blockIdx.x * 256 + threadIdx.x) >> 5;
    const int lane = threadIdx.x & 31;
    if (row >= owned) return;
    const int s = __ldg(rs + row);
    const int e = __ldg(rs + row + 1);

    float4 a0 = make_float4(0.f, 0.f, 0.f, 0.f);
    float4 a1 = make_float4(0.f, 0.f, 0.f, 0.f);
    int j = s;
    for (; j + 1 < e; j += 2) {
        const int c0 = __ldg(cols + j);
        const int c1 = __ldg(cols + j + 1);
        const float4 v0 = *(const float4*)(H + (size_t)c0 * C1 + lane * 4);
        const float4 v1 = *(const float4*)(H + (size_t)c1 * C1 + lane * 4);
        a0.x += v0.x; a0.y += v0.y; a0.z += v0.z; a0.w += v0.w;
        a1.x += v1.x; a1.y += v1.y; a1.z += v1.z; a1.w += v1.w;
    }
    if (j < e) {
        const int c0 = __ldg(cols + j);
        const float4 v0 = *(const float4*)(H + (size_t)c0 * C1 + lane * 4);
        a0.x += v0.x; a0.y += v0.y; a0.z += v0.z; a0.w += v0.w;
    }
    const float d = __ldg(deg + row);
    const float4 bb = ((const float4*)b)[lane];
    float4 o;
    o.x = fmaxf(fmaf(a0.x + a1.x, d, bb.x), 0.f);
    o.y = fmaxf(fmaf(a0.y + a1.y, d, bb.y), 0.f);
    o.z = fmaxf(fmaf(a0.z + a1.z, d, bb.z), 0.f);
    o.w = fmaxf(fmaf(a0.w + a1.w, d, bb.w), 0.f);
    *(float4*)(x2 + (size_t)row * C1 + lane * 4) = o;
}

// ===========================================================================
// Gather layer 2: out[row,:] = (sum_{col_j<owned} h2[col_j,:])*deg[row] + b2
// ===========================================================================
__global__ __launch_bounds__(256) void gather_out(
    const float* __restrict__ H, const int* __restrict__ rs,
    const int* __restrict__ cols, const float* __restrict__ deg,
    const float* __restrict__ b, float* __restrict__ out, int owned)
{
    const int row  = (blockIdx.x * 256 + threadIdx.x) >> 5;
    const int lane = threadIdx.x & 31;
    if (row >= owned) return;
    const int s = __ldg(rs + row);
    const int e = __ldg(rs + row + 1);

    float2 a0 = make_float2(0.f, 0.f);
    float2 a1 = make_float2(0.f, 0.f);
    int j = s;
    for (; j + 1 < e; j += 2) {
        const int c0 = __ldg(cols + j);
        const int c1 = __ldg(cols + j + 1);
        if (c0 < owned) {
            const float2 v = *(const float2*)(H + (size_t)c0 * C2 + lane * 2);
            a0.x += v.x; a0.y += v.y;
        }
        if (c1 < owned) {
            const float2 v = *(const float2*)(H + (size_t)c1 * C2 + lane * 2);
            a1.x += v.x; a1.y += v.y;
        }
    }
    if (j < e) {
        const int c0 = __ldg(cols + j);
        if (c0 < owned) {
            const float2 v = *(const float2*)(H + (size_t)c0 * C2 + lane * 2);
            a0.x += v.x; a0.y += v.y;
        }
    }
    const float d = __ldg(deg + row);
    const float2 bb = ((const float2*)b)[lane];
    float2 o;
    o.x = fmaf(a0.x + a1.x, d, bb.x);
    o.y = fmaf(a0.y + a1.y, d, bb.y);
    *(float2*)(out + (size_t)row * C2 + lane * 2) = o;
}

// ===========================================================================
extern "C" void kernel_launch(void* const* d_in, const int* in_sizes, int n_in,
                              void* d_out, int out_size)
{
    const float* x   = (const float*)d_in[0];
    const float* deg = (const float*)d_in[1];
    const float* w1  = (const float*)d_in[2];
    const float* b1  = (const float*)d_in[3];
    const float* w2  = (const float*)d_in[4];
    const float* b2  = (const float*)d_in[5];
    const int*   er  = (const int*)d_in[6];
    const int*   ec  = (const int*)d_in[7];

    const int nloc  = in_sizes[0] / C1;     // 55000
    const int nE    = in_sizes[6];          // 800000
    const int owned = out_size / C2;        // 50000
    float* out = (float*)d_out;

    float *p_h, *p_x2, *p_h2;
    int *p_rs, *p_cur, *p_col, *p_meta;
    cudaGetSymbolAddress((void**)&p_h,    g_h);
    cudaGetSymbolAddress((void**)&p_x2,   g_x2);
    cudaGetSymbolAddress((void**)&p_h2,   g_h2);
    cudaGetSymbolAddress((void**)&p_rs,   g_rowstart);
    cudaGetSymbolAddress((void**)&p_cur,  g_cursor);
    cudaGetSymbolAddress((void**)&p_col,  g_csrcol);
    cudaGetSymbolAddress((void**)&p_meta, g_meta);

    int* p_hist  = p_meta;
    int* p_flags = p_meta + MAX_LOCAL;
    int* p_agg   = p_meta + MAX_LOCAL + 64;
    int* p_pfx   = p_meta + MAX_LOCAL + 128;

    // ---- CSR build (4 nodes) ----
    cudaMemsetAsync(p_meta, 0, (size_t)(MAX_LOCAL + 64) * sizeof(int), 0);
    edge_hist<<<(nE + 255) / 256, 256>>>(er, p_hist, nE);
    const int nB = (nloc + 1023) / 1024;
    scan_csr<<<nB, 1024>>>(p_hist, p_rs, p_cur, p_flags, p_agg, p_pfx, nloc);
    csr_fill<<<(nE + 255) / 256, 256>>>(er, ec, p_cur, p_col, nE);

    // ---- Layer 1 ----
    {
        dim3 g((nloc + 127) / 128, C1 / 64);
        gemm_tf32<<<g, 256>>>(x, w1, deg, p_h, nloc, C1);
    }
    gather_relu<<<(owned * 32 + 255) / 256, 256>>>(p_h, p_rs, p_col, deg, b1, p_x2, owned);

    // ---- Layer 2 (owned rows only) ----
    {
        dim3 g((owned + 127) / 128, 1);
        gemm_tf32<<<g, 256>>>(p_x2, w2, deg, p_h2, owned, C2);
    }
    gather_out<<<(owned * 32 + 255) / 256, 256>>>(p_h2, p_rs, p_col, deg, b2, out, owned);
}

// round 5
// speedup vs baseline: 2.4650x; 1.3461x over previous
#include <cuda_runtime.h>
#include <cuda_fp16.h>
#include <cstdint>

#define MAX_LOCAL 55000
#define MAX_EDGES 800000
#define C1 128
#define C2 64

// ---- static scratch (allocation-free) ----
__device__ __half g_h  [MAX_LOCAL * C1];     // (X W1) * deg   (fp16)
__device__ __half g_x2 [MAX_LOCAL * C1];     // relu output    (fp16)
__device__ __half g_h2 [MAX_LOCAL * C2];     // (X2 W2) * deg  (fp16)
__device__ int    g_rowstart[MAX_LOCAL + 1];
__device__ int    g_cursor  [MAX_LOCAL];
__device__ int    g_csrcol  [MAX_EDGES];
// meta: [0,MAX_LOCAL) hist | +64 flags | +64 agg | +64 pfx
__device__ int    g_meta[MAX_LOCAL + 192];

// ===========================================================================
// CSR build
// ===========================================================================
__global__ __launch_bounds__(256) void edge_hist(
    const int* __restrict__ er, int* __restrict__ cnt, int nE)
{
    int e = blockIdx.x * blockDim.x + threadIdx.x;
    if (e < nE) atomicAdd(&cnt[er[e]], 1);
}

__global__ __launch_bounds__(1024) void scan_csr(
    const int* __restrict__ cnt, int* __restrict__ rs, int* __restrict__ cur,
    int* flags, int* agg, int* pfx, int n)
{
    __shared__ int wsum[32];
    __shared__ int s_excl;
    const int b = blockIdx.x, t = threadIdx.x;
    const int i = b * 1024 + t;
    const int lane = t & 31, wid = t >> 5;

    int v = (i < n) ? cnt[i] : 0;
    int incl = v;
#pragma unroll
    for (int o = 1; o < 32; o <<= 1) {
        int u = __shfl_up_sync(~0u, incl, o);
        if (lane >= o) incl += u;
    }
    if (lane == 31) wsum[wid] = incl;
    __syncthreads();
    if (wid == 0) {
        int ws = wsum[lane];
#pragma unroll
        for (int o = 1; o < 32; o <<= 1) {
            int u = __shfl_up_sync(~0u, ws, o);
            if (lane >= o) ws += u;
        }
        wsum[lane] = ws;
    }
    __syncthreads();
    const int blockIncl = incl + (wid ? wsum[wid - 1] : 0);
    const int total = wsum[31];

    if (t == 0) {
        agg[b] = total;
        __threadfence();
        ((volatile int*)flags)[b] = 1;
        int ex = 0;
        for (int p = b - 1; p >= 0; --p) {
            int f;
            do { f = ((volatile int*)flags)[p]; } while (f == 0);
            __threadfence();
            if (f == 2) { ex += pfx[p]; break; }
            ex += agg[p];
        }
        pfx[b] = ex + total;
        __threadfence();
        ((volatile int*)flags)[b] = 2;
        s_excl = ex;
    }
    __syncthreads();
    if (i < n) {
        const int base = s_excl + blockIncl - v;
        rs[i]  = base;
        cur[i] = base;
    }
}

__global__ __launch_bounds__(256) void csr_fill(
    const int* __restrict__ er, const int* __restrict__ ec,
    int* __restrict__ cursor, int* __restrict__ col, int nE)
{
    int e = blockIdx.x * blockDim.x + threadIdx.x;
    if (e < nE) {
        int p = atomicAdd(&cursor[er[e]], 1);
        col[p] = ec[e];
    }
}

// ===========================================================================
// fp16 tensor-core GEMM with ldmatrix + SW128 swizzle + double buffering
// out[r, nb:nb+64] = fp16( (X[r,:128] @ W[:,nb:nb+64]) * deg[r] )
// Block: 256 thr = 8 warps (4m x 2n). BM=128, BN=64, BK=64, K=128 (2 iters).
// ===========================================================================
__device__ __forceinline__ void ldsm4(unsigned& r0, unsigned& r1,
                                      unsigned& r2, unsigned& r3, unsigned a) {
    asm volatile("ldmatrix.sync.aligned.m8n8.x4.shared.b16 {%0,%1,%2,%3}, [%4];"
                 : "=r"(r0), "=r"(r1), "=r"(r2), "=r"(r3) : "r"(a));
}
__device__ __forceinline__ void ldsm4t(unsigned& r0, unsigned& r1,
                                       unsigned& r2, unsigned& r3, unsigned a) {
    asm volatile("ldmatrix.sync.aligned.m8n8.x4.trans.shared.b16 {%0,%1,%2,%3}, [%4];"
                 : "=r"(r0), "=r"(r1), "=r"(r2), "=r"(r3) : "r"(a));
}
__device__ __forceinline__ void mma16816(float& c0, float& c1, float& c2, float& c3,
                                         unsigned a0, unsigned a1, unsigned a2, unsigned a3,
                                         unsigned b0, unsigned b1) {
    asm volatile("mma.sync.aligned.m16n8k16.row.col.f32.f16.f16.f32 "
                 "{%0,%1,%2,%3}, {%4,%5,%6,%7}, {%8,%9}, {%0,%1,%2,%3};"
                 : "+f"(c0), "+f"(c1), "+f"(c2), "+f"(c3)
                 : "r"(a0), "r"(a1), "r"(a2), "r"(a3), "r"(b0), "r"(b1));
}

// smem layout: A0[16K] A1[16K] B0[8K] B1[8K] = 48KB
#define A_OFF(buf) ((buf) * 16384)
#define B_OFF(buf) (32768 + (buf) * 8192)

template<bool AHALF>
__global__ __launch_bounds__(256) void gemm_f16(
    const void* __restrict__ Xv, const float* __restrict__ W,
    const float* __restrict__ deg, __half* __restrict__ out,
    int rows, int n_ld)
{
    constexpr int K = 128, BK = 64, BM = 128;
    __shared__ __align__(16) char smem[49152];
    const unsigned sbase = (unsigned)__cvta_generic_to_shared(smem);

    const int t     = threadIdx.x;
    const int warp  = t >> 5;
    const int lane  = t & 31;
    const int warpM = warp >> 1;
    const int warpN = warp & 1;
    const int rbase = blockIdx.x * BM;
    const int nbase = blockIdx.y * 64;

    float acc[2][4][4];
#pragma unroll
    for (int mt = 0; mt < 2; ++mt)
#pragma unroll
        for (int nt = 0; nt < 4; ++nt)
#pragma unroll
            for (int c = 0; c < 4; ++c) acc[mt][nt][c] = 0.f;

    // ---- tile loader ----
    auto load_tiles = [&](int buf, int kb) {
        // A tile -> [128 rows][64 halfs] swizzled
        if constexpr (!AHALF) {
            const float* X = (const float*)Xv;
            const int rr0 = t >> 4, six = t & 15;
            const int chunk = six >> 1, sub = six & 1;
#pragma unroll
            for (int p = 0; p < 8; ++p) {
                const int rr = p * 16 + rr0;
                const int grow = rbase + rr;
                float4 v = make_float4(0.f, 0.f, 0.f, 0.f);
                if (grow < rows)
                    v = *(const float4*)(X + (size_t)grow * K + kb + six * 4);
                __half2 h0 = __floats2half2_rn(v.x, v.y);
                __half2 h1 = __floats2half2_rn(v.z, v.w);
                uint2 u;
                u.x = *(unsigned*)&h0; u.y = *(unsigned*)&h1;
                *(uint2*)(smem + A_OFF(buf) + rr * 128 +
                          ((chunk ^ (rr & 7)) << 4) + sub * 8) = u;
            }
        } else {
            const __half* X = (const __half*)Xv;
            const int rr0 = t >> 3, oct = t & 7;
#pragma unroll
            for (int p = 0; p < 4; ++p) {
                const int rr = p * 32 + rr0;
                const int grow = rbase + rr;
                uint4 v = make_uint4(0u, 0u, 0u, 0u);
                if (grow < rows)
                    v = *(const uint4*)(X + (size_t)grow * K + kb + oct * 8);
                *(uint4*)(smem + A_OFF(buf) + rr * 128 +
                          ((oct ^ (rr & 7)) << 4)) = v;
            }
        }
        // B tile: W rows kb..kb+63, cols nbase..nbase+63 -> [64 k][64 n] swizzled
        {
            const int kr0 = t >> 4, six = t & 15;
            const int chunk = six >> 1, sub = six & 1;
#pragma unroll
            for (int p = 0; p < 4; ++p) {
                const int kr = p * 16 + kr0;
                const float4 v = *(const float4*)(W + (size_t)(kb + kr) * n_ld + nbase + six * 4);
                __half2 h0 = __floats2half2_rn(v.x, v.y);
                __half2 h1 = __floats2half2_rn(v.z, v.w);
                uint2 u;
                u.x = *(unsigned*)&h0; u.y = *(unsigned*)&h1;
                *(uint2*)(smem + B_OFF(buf) + kr * 128 +
                          ((chunk ^ (kr & 7)) << 4) + sub * 8) = u;
            }
        }
    };

    // ---- per-thread fragment address invariants ----
    int rA[2], rA7[2];
#pragma unroll
    for (int mt = 0; mt < 2; ++mt) {
        rA[mt]  = warpM * 32 + mt * 16 + (lane & 15);
        rA7[mt] = rA[mt] & 7;
    }
    const int krow_l = lane & 15;
    const int hi     = lane >> 4;
    int nchB[2];
#pragma unroll
    for (int nt2 = 0; nt2 < 2; ++nt2)
        nchB[nt2] = ((warpN * 32 + nt2 * 16) >> 3) + hi;

    auto compute = [&](int buf) {
        const unsigned aB = sbase + A_OFF(buf);
        const unsigned bB = sbase + B_OFF(buf);
#pragma unroll
        for (int step = 0; step < 4; ++step) {
            unsigned a[2][4], bq[2][4];
#pragma unroll
            for (int mt = 0; mt < 2; ++mt) {
                const unsigned addr = aB + rA[mt] * 128 +
                                      (((step * 2 + hi) ^ rA7[mt]) << 4);
                ldsm4(a[mt][0], a[mt][1], a[mt][2], a[mt][3], addr);
            }
#pragma unroll
            for (int nt2 = 0; nt2 < 2; ++nt2) {
                const int kr = step * 16 + krow_l;
                const unsigned addr = bB + kr * 128 +
                                      ((nchB[nt2] ^ (kr & 7)) << 4);
                ldsm4t(bq[nt2][0], bq[nt2][1], bq[nt2][2], bq[nt2][3], addr);
            }
#pragma unroll
            for (int mt = 0; mt < 2; ++mt)
#pragma unroll
                for (int nt = 0; nt < 4; ++nt)
                    mma16816(acc[mt][nt][0], acc[mt][nt][1],
                             acc[mt][nt][2], acc[mt][nt][3],
                             a[mt][0], a[mt][1], a[mt][2], a[mt][3],
                             bq[nt >> 1][(nt & 1) * 2], bq[nt >> 1][(nt & 1) * 2 + 1]);
        }
    };

    // ---- double-buffered K loop (2 iterations) ----
    load_tiles(0, 0);
    __syncthreads();
    load_tiles(1, BK);
    compute(0);
    __syncthreads();
    compute(1);

    // ---- epilogue: *deg, convert fp16, store half2 ----
    const int g  = lane >> 2;
    const int tq = lane & 3;
#pragma unroll
    for (int mt = 0; mt < 2; ++mt) {
        const int r0 = rbase + warpM * 32 + mt * 16 + g;
        const int r1 = r0 + 8;
        const float d0 = (r0 < rows) ? deg[r0] : 0.f;
        const float d1 = (r1 < rows) ? deg[r1] : 0.f;
#pragma unroll
        for (int nt = 0; nt < 4; ++nt) {
            const int cc = nbase + warpN * 32 + nt * 8 + tq * 2;
            if (r0 < rows) {
                __half2 h = __floats2half2_rn(acc[mt][nt][0] * d0, acc[mt][nt][1] * d0);
                *(__half2*)(out + (size_t)r0 * n_ld + cc) = h;
            }
            if (r1 < rows) {
                __half2 h = __floats2half2_rn(acc[mt][nt][2] * d1, acc[mt][nt][3] * d1);
                *(__half2*)(out + (size_t)r1 * n_ld + cc) = h;
            }
        }
    }
}

// ===========================================================================
// Gather 1: x2[row,:] = fp16( relu( (sum_j h[col_j,:]) * deg[row] + b1 ) )
// warp/row; lane covers 4 channels (uint2 = 4 halfs)
// ===========================================================================
__global__ __launch_bounds__(256) void gather_relu(
    const __half* __restrict__ H, const int* __restrict__ rs,
    const int* __restrict__ cols, const float* __restrict__ deg,
    const float* __restrict__ b, __half* __restrict__ x2, int owned)
{
    const int row  = (blockIdx.x * 256 + threadIdx.x) >> 5;
    const int lane = threadIdx.x & 31;
    if (row >= owned) return;
    const int s = __ldg(rs + row);
    const int e = __ldg(rs + row + 1);

    float a0 = 0.f, a1 = 0.f, a2 = 0.f, a3 = 0.f;
    int j = s;
    for (; j + 1 < e; j += 2) {
        const int c0 = __ldg(cols + j);
        const int c1 = __ldg(cols + j + 1);
        const uint2 u0 = *(const uint2*)(H + (size_t)c0 * C1 + lane * 4);
        const uint2 u1 = *(const uint2*)(H + (size_t)c1 * C1 + lane * 4);
        float2 f;
        f = __half22float2(*(const __half2*)&u0.x); a0 += f.x; a1 += f.y;
        f = __half22float2(*(const __half2*)&u0.y); a2 += f.x; a3 += f.y;
        f = __half22float2(*(const __half2*)&u1.x); a0 += f.x; a1 += f.y;
        f = __half22float2(*(const __half2*)&u1.y); a2 += f.x; a3 += f.y;
    }
    if (j < e) {
        const int c0 = __ldg(cols + j);
        const uint2 u0 = *(const uint2*)(H + (size_t)c0 * C1 + lane * 4);
        float2 f;
        f = __half22float2(*(const __half2*)&u0.x); a0 += f.x; a1 += f.y;
        f = __half22float2(*(const __half2*)&u0.y); a2 += f.x; a3 += f.y;
    }
    const float d = __ldg(deg + row);
    const float4 bb = ((const float4*)b)[lane];
    __half2 o0 = __floats2half2_rn(fmaxf(fmaf(a0, d, bb.x), 0.f),
                                   fmaxf(fmaf(a1, d, bb.y), 0.f));
    __half2 o1 = __floats2half2_rn(fmaxf(fmaf(a2, d, bb.z), 0.f),
                                   fmaxf(fmaf(a3, d, bb.w), 0.f));
    uint2 u;
    u.x = *(unsigned*)&o0; u.y = *(unsigned*)&o1;
    *(uint2*)(x2 + (size_t)row * C1 + lane * 4) = u;
}

// ===========================================================================
// Gather 2: out[row,:] = (sum_{col_j<owned} h2[col_j,:]) * deg[row] + b2
// warp/row; lane covers 2 channels (half2)
// ===========================================================================
__global__ __launch_bounds__(256) void gather_out(
    const __half* __restrict__ H, const int* __restrict__ rs,
    const int* __restrict__ cols, const float* __restrict__ deg,
    const float* __restrict__ b, float* __restrict__ out, int owned)
{
    const int row  = (blockIdx.x * 256 + threadIdx.x) >> 5;
    const int lane = threadIdx.x & 31;
    if (row >= owned) return;
    const int s = __ldg(rs + row);
    const int e = __ldg(rs + row + 1);

    float a0 = 0.f, a1 = 0.f, b0 = 0.f, b1 = 0.f;
    int j = s;
    for (; j + 1 < e; j += 2) {
        const int c0 = __ldg(cols + j);
        const int c1 = __ldg(cols + j + 1);
        if (c0 < owned) {
            float2 f = __half22float2(*(const __half2*)(H + (size_t)c0 * C2 + lane * 2));
            a0 += f.x; a1 += f.y;
        }
        if (c1 < owned) {
            float2 f = __half22float2(*(const __half2*)(H + (size_t)c1 * C2 + lane * 2));
            b0 += f.x; b1 += f.y;
        }
    }
    if (j < e) {
        const int c0 = __ldg(cols + j);
        if (c0 < owned) {
            float2 f = __half22float2(*(const __half2*)(H + (size_t)c0 * C2 + lane * 2));
            a0 += f.x; a1 += f.y;
        }
    }
    const float d = __ldg(deg + row);
    const float2 bb = ((const float2*)b)[lane];
    float2 o;
    o.x = fmaf(a0 + b0, d, bb.x);
    o.y = fmaf(a1 + b1, d, bb.y);
    *(float2*)(out + (size_t)row * C2 + lane * 2) = o;
}

// ===========================================================================
extern "C" void kernel_launch(void* const* d_in, const int* in_sizes, int n_in,
                              void* d_out, int out_size)
{
    const float* x   = (const float*)d_in[0];
    const float* deg = (const float*)d_in[1];
    const float* w1  = (const float*)d_in[2];
    const float* b1  = (const float*)d_in[3];
    const float* w2  = (const float*)d_in[4];
    const float* b2  = (const float*)d_in[5];
    const int*   er  = (const int*)d_in[6];
    const int*   ec  = (const int*)d_in[7];

    const int nloc  = in_sizes[0] / C1;     // 55000
    const int nE    = in_sizes[6];          // 800000
    const int owned = out_size / C2;        // 50000
    float* out = (float*)d_out;

    __half *p_h, *p_x2, *p_h2;
    int *p_rs, *p_cur, *p_col, *p_meta;
    cudaGetSymbolAddress((void**)&p_h,    g_h);
    cudaGetSymbolAddress((void**)&p_x2,   g_x2);
    cudaGetSymbolAddress((void**)&p_h2,   g_h2);
    cudaGetSymbolAddress((void**)&p_rs,   g_rowstart);
    cudaGetSymbolAddress((void**)&p_cur,  g_cursor);
    cudaGetSymbolAddress((void**)&p_col,  g_csrcol);
    cudaGetSymbolAddress((void**)&p_meta, g_meta);

    int* p_hist  = p_meta;
    int* p_flags = p_meta + MAX_LOCAL;
    int* p_agg   = p_meta + MAX_LOCAL + 64;
    int* p_pfx   = p_meta + MAX_LOCAL + 128;

    // ---- CSR build ----
    cudaMemsetAsync(p_meta, 0, (size_t)(MAX_LOCAL + 64) * sizeof(int), 0);
    edge_hist<<<(nE + 255) / 256, 256>>>(er, p_hist, nE);
    const int nB = (nloc + 1023) / 1024;
    scan_csr<<<nB, 1024>>>(p_hist, p_rs, p_cur, p_flags, p_agg, p_pfx, nloc);
    csr_fill<<<(nE + 255) / 256, 256>>>(er, ec, p_cur, p_col, nE);

    // ---- Layer 1 ----
    {
        dim3 g((nloc + 127) / 128, C1 / 64);
        gemm_f16<false><<<g, 256>>>(x, w1, deg, p_h, nloc, C1);
    }
    gather_relu<<<(owned * 32 + 255) / 256, 256>>>(p_h, p_rs, p_col, deg, b1, p_x2, owned);

    // ---- Layer 2 (owned rows only) ----
    {
        dim3 g((owned + 127) / 128, 1);
        gemm_f16<true><<<g, 256>>>(p_x2, w2, deg, p_h2, owned, C2);
    }
    gather_out<<<(owned * 32 + 255) / 256, 256>>>(p_h2, p_rs, p_col, deg, b2, out, owned);
}

// round 8
// speedup vs baseline: 2.7075x; 1.0984x over previous
#include <cuda_runtime.h>
#include <cuda_fp16.h>
#include <cstdint>

#define MAX_LOCAL 55000
#define MAX_EDGES 800000
#define C1 128
#define C2 64

// ---- static scratch (allocation-free) ----
__device__ __half g_xh [MAX_LOCAL * C1];     // fp16 copy of X
__device__ __half g_h  [MAX_LOCAL * C1];     // (X W1) * deg   (fp16)
__device__ __half g_x2 [MAX_LOCAL * C1];     // relu output    (fp16)
__device__ __half g_h2 [MAX_LOCAL * C2];     // (X2 W2) * deg  (fp16)
__device__ int    g_rowstart[MAX_LOCAL + 1];
__device__ int    g_cursor  [MAX_LOCAL];
__device__ int    g_csrcol  [MAX_EDGES];
// meta: [0,MAX_LOCAL) hist | +64 flags | +64 agg | +64 pfx
__device__ int    g_meta[MAX_LOCAL + 192];

// ===========================================================================
// X fp32 -> fp16 convert (streaming)
// ===========================================================================
__global__ __launch_bounds__(256) void conv_half(
    const float* __restrict__ X, __half* __restrict__ Xh, int n8)
{
    const int i = blockIdx.x * blockDim.x + threadIdx.x;
    if (i >= n8) return;
    const float4 v0 = ((const float4*)X)[i * 2];
    const float4 v1 = ((const float4*)X)[i * 2 + 1];
    __half2 h0 = __floats2half2_rn(v0.x, v0.y);
    __half2 h1 = __floats2half2_rn(v0.z, v0.w);
    __half2 h2 = __floats2half2_rn(v1.x, v1.y);
    __half2 h3 = __floats2half2_rn(v1.z, v1.w);
    uint4 u;
    u.x = *(unsigned*)&h0; u.y = *(unsigned*)&h1;
    u.z = *(unsigned*)&h2; u.w = *(unsigned*)&h3;
    ((uint4*)Xh)[i] = u;
}

// ===========================================================================
// CSR build
// ===========================================================================
__global__ __launch_bounds__(256) void edge_hist(
    const int* __restrict__ er, int* __restrict__ cnt, int nE)
{
    int e = blockIdx.x * blockDim.x + threadIdx.x;
    if (e < nE) atomicAdd(&cnt[er[e]], 1);
}

__global__ __launch_bounds__(1024) void scan_csr(
    const int* __restrict__ cnt, int* __restrict__ rs, int* __restrict__ cur,
    int* flags, int* agg, int* pfx, int n)
{
    __shared__ int wsum[32];
    __shared__ int s_excl;
    const int b = blockIdx.x, t = threadIdx.x;
    const int i = b * 1024 + t;
    const int lane = t & 31, wid = t >> 5;

    int v = (i < n) ? cnt[i] : 0;
    int incl = v;
#pragma unroll
    for (int o = 1; o < 32; o <<= 1) {
        int u = __shfl_up_sync(~0u, incl, o);
        if (lane >= o) incl += u;
    }
    if (lane == 31) wsum[wid] = incl;
    __syncthreads();
    if (wid == 0) {
        int ws = wsum[lane];
#pragma unroll
        for (int o = 1; o < 32; o <<= 1) {
            int u = __shfl_up_sync(~0u, ws, o);
            if (lane >= o) ws += u;
        }
        wsum[lane] = ws;
    }
    __syncthreads();
    const int blockIncl = incl + (wid ? wsum[wid - 1] : 0);
    const int total = wsum[31];

    if (t == 0) {
        agg[b] = total;
        __threadfence();
        ((volatile int*)flags)[b] = 1;
        int ex = 0;
        for (int p = b - 1; p >= 0; --p) {
            int f;
            do { f = ((volatile int*)flags)[p]; } while (f == 0);
            __threadfence();
            if (f == 2) { ex += pfx[p]; break; }
            ex += agg[p];
        }
        pfx[b] = ex + total;
        __threadfence();
        ((volatile int*)flags)[b] = 2;
        s_excl = ex;
    }
    __syncthreads();
    if (i < n) {
        const int base = s_excl + blockIncl - v;
        rs[i]  = base;
        cur[i] = base;
    }
}

__global__ __launch_bounds__(256) void csr_fill(
    const int* __restrict__ er, const int* __restrict__ ec,
    int* __restrict__ cursor, int* __restrict__ col, int nE)
{
    int e = blockIdx.x * blockDim.x + threadIdx.x;
    if (e < nE) {
        int p = atomicAdd(&cursor[er[e]], 1);
        col[p] = ec[e];
    }
}

// ===========================================================================
// fp16 tensor GEMM, A fp16 via cp.async, W fp32 converted on load.
// out[r, nb:nb+64] = fp16( (X[r,:128] @ W[:,nb:nb+64]) * deg[r] )
// 256 thr = 8 warps (4m x 2n). BM=128, BN=64, BK=64, K=128 (2 iters).
// ===========================================================================
__device__ __forceinline__ void ldsm4(unsigned& r0, unsigned& r1,
                                      unsigned& r2, unsigned& r3, unsigned a) {
    asm volatile("ldmatrix.sync.aligned.m8n8.x4.shared.b16 {%0,%1,%2,%3}, [%4];"
                 : "=r"(r0), "=r"(r1), "=r"(r2), "=r"(r3) : "r"(a));
}
__device__ __forceinline__ void ldsm4t(unsigned& r0, unsigned& r1,
                                       unsigned& r2, unsigned& r3, unsigned a) {
    asm volatile("ldmatrix.sync.aligned.m8n8.x4.trans.shared.b16 {%0,%1,%2,%3}, [%4];"
                 : "=r"(r0), "=r"(r1), "=r"(r2), "=r"(r3) : "r"(a));
}
__device__ __forceinline__ void mma16816(float& c0, float& c1, float& c2, float& c3,
                                         unsigned a0, unsigned a1, unsigned a2, unsigned a3,
                                         unsigned b0, unsigned b1) {
    asm volatile("mma.sync.aligned.m16n8k16.row.col.f32.f16.f16.f32 "
                 "{%0,%1,%2,%3}, {%4,%5,%6,%7}, {%8,%9}, {%0,%1,%2,%3};"
                 : "+f"(c0), "+f"(c1), "+f"(c2), "+f"(c3)
                 : "r"(a0), "r"(a1), "r"(a2), "r"(a3), "r"(b0), "r"(b1));
}
__device__ __forceinline__ void cpa16(unsigned dst, const void* src, bool p) {
    int sz = p ? 16 : 0;
    asm volatile("cp.async.cg.shared.global [%0], [%1], 16, %2;"
                 :: "r"(dst), "l"(src), "r"(sz));
}

// smem: A0[16K] A1[16K] B0[8K] B1[8K] = 48KB
#define A_OFF(buf) ((buf) * 16384)
#define B_OFF(buf) (32768 + (buf) * 8192)

__global__ __launch_bounds__(256) void gemm_f16(
    const __half* __restrict__ X, const float* __restrict__ W,
    const float* __restrict__ deg, __half* __restrict__ out,
    int rows, int n_ld)
{
    constexpr int K = 128, BK = 64;
    __shared__ __align__(16) char smem[49152];
    const unsigned sbase = (unsigned)__cvta_generic_to_shared(smem);

    const int t     = threadIdx.x;
    const int warp  = t >> 5;
    const int lane  = t & 31;
    const int warpM = warp >> 1;
    const int warpN = warp & 1;
    const int rbase = blockIdx.x * 128;
    const int nbase = blockIdx.y * 64;

    float acc[2][4][4];
#pragma unroll
    for (int mt = 0; mt < 2; ++mt)
#pragma unroll
        for (int nt = 0; nt < 4; ++nt)
#pragma unroll
            for (int c = 0; c < 4; ++c) acc[mt][nt][c] = 0.f;

    // A tile via cp.async (fp16 rows, stride K=128 halfs)
    auto load_a = [&](int buf, int kb) {
        const int rr0 = t >> 3, oct = t & 7;
#pragma unroll
        for (int p = 0; p < 4; ++p) {
            const int rr = p * 32 + rr0;
            const int grow = rbase + rr;
            const unsigned dst = sbase + A_OFF(buf) + rr * 128 +
                                 ((oct ^ (rr & 7)) << 4);
            cpa16(dst, X + (size_t)grow * K + kb + oct * 8, grow < rows);
        }
    };
    // B tile: W fp32 rows kb..kb+63, cols nbase..+64 -> fp16 swizzled
    auto load_b = [&](int buf, int kb) {
        const int kr0 = t >> 4, six = t & 15;
        const int chunk = six >> 1, sub = six & 1;
#pragma unroll
        for (int p = 0; p < 4; ++p) {
            const int kr = p * 16 + kr0;
            const float4 v = *(const float4*)(W + (size_t)(kb + kr) * n_ld + nbase + six * 4);
            __half2 h0 = __floats2half2_rn(v.x, v.y);
            __half2 h1 = __floats2half2_rn(v.z, v.w);
            uint2 u;
            u.x = *(unsigned*)&h0; u.y = *(unsigned*)&h1;
            *(uint2*)(smem + B_OFF(buf) + kr * 128 +
                      ((chunk ^ (kr & 7)) << 4) + sub * 8) = u;
        }
    };

    int rA[2], rA7[2];
#pragma unroll
    for (int mt = 0; mt < 2; ++mt) {
        rA[mt]  = warpM * 32 + mt * 16 + (lane & 15);
        rA7[mt] = rA[mt] & 7;
    }
    const int krow_l = lane & 15;
    const int hi     = lane >> 4;
    int nchB[2];
#pragma unroll
    for (int nt2 = 0; nt2 < 2; ++nt2)
        nchB[nt2] = ((warpN * 32 + nt2 * 16) >> 3) + hi;

    auto compute = [&](int buf) {
        const unsigned aB = sbase + A_OFF(buf);
        const unsigned bB = sbase + B_OFF(buf);
#pragma unroll
        for (int step = 0; step < 4; ++step) {
            unsigned a[2][4], bq[2][4];
#pragma unroll
            for (int mt = 0; mt < 2; ++mt) {
                const unsigned addr = aB + rA[mt] * 128 +
                                      (((step * 2 + hi) ^ rA7[mt]) << 4);
                ldsm4(a[mt][0], a[mt][1], a[mt][2], a[mt][3], addr);
            }
#pragma unroll
            for (int nt2 = 0; nt2 < 2; ++nt2) {
                const int kr = step * 16 + krow_l;
                const unsigned addr = bB + kr * 128 +
                                      ((nchB[nt2] ^ (kr & 7)) << 4);
                ldsm4t(bq[nt2][0], bq[nt2][1], bq[nt2][2], bq[nt2][3], addr);
            }
#pragma unroll
            for (int mt = 0; mt < 2; ++mt)
#pragma unroll
                for (int nt = 0; nt < 4; ++nt)
                    mma16816(acc[mt][nt][0], acc[mt][nt][1],
                             acc[mt][nt][2], acc[mt][nt][3],
                             a[mt][0], a[mt][1], a[mt][2], a[mt][3],
                             bq[nt >> 1][(nt & 1) * 2], bq[nt >> 1][(nt & 1) * 2 + 1]);
        }
    };

    // pipeline: A0 async + A1 async (grouped), B sync
    load_a(0, 0);
    asm volatile("cp.async.commit_group;");
    load_a(1, BK);
    asm volatile("cp.async.commit_group;");
    load_b(0, 0);
    asm volatile("cp.async.wait_group 1;");
    __syncthreads();
    compute(0);
    load_b(1, BK);
    asm volatile("cp.async.wait_group 0;");
    __syncthreads();
    compute(1);

    // epilogue
    const int g  = lane >> 2;
    const int tq = lane & 3;
#pragma unroll
    for (int mt = 0; mt < 2; ++mt) {
        const int r0 = rbase + warpM * 32 + mt * 16 + g;
        const int r1 = r0 + 8;
        const float d0 = (r0 < rows) ? deg[r0] : 0.f;
        const float d1 = (r1 < rows) ? deg[r1] : 0.f;
#pragma unroll
        for (int nt = 0; nt < 4; ++nt) {
            const int cc = nbase + warpN * 32 + nt * 8 + tq * 2;
            if (r0 < rows) {
                __half2 h = __floats2half2_rn(acc[mt][nt][0] * d0, acc[mt][nt][1] * d0);
                *(__half2*)(out + (size_t)r0 * n_ld + cc) = h;
            }
            if (r1 < rows) {
                __half2 h = __floats2half2_rn(acc[mt][nt][2] * d1, acc[mt][nt][3] * d1);
                *(__half2*)(out + (size_t)r1 * n_ld + cc) = h;
            }
        }
    }
}

// ===========================================================================
// Gather 1: x2[row,:] = fp16( relu( (sum_j h[col_j,:]) * deg[row] + b1 ) )
// warp/row, 4-edge unroll, uint2 (4 halfs) per lane
// ===========================================================================
__global__ __launch_bounds__(256) void gather_relu(
    const __half* __restrict__ H, const int* __restrict__ rs,
    const int* __restrict__ cols, const float* __restrict__ deg,
    const float* __restrict__ b, __half* __restrict__ x2, int owned)
{
    const int row  = (blockIdx.x * 256 + threadIdx.x) >> 5;
    const int lane = threadIdx.x & 31;
    if (row >= owned) return;
    const int s = __ldg(rs + row);
    const int e = __ldg(rs + row + 1);

    float a0 = 0.f, a1 = 0.f, a2 = 0.f, a3 = 0.f;
    int j = s;
    for (; j + 3 < e; j += 4) {
        int c0 = __ldg(cols + j),     c1 = __ldg(cols + j + 1);
        int c2 = __ldg(cols + j + 2), c3 = __ldg(cols + j + 3);
        const uint2 u0 = *(const uint2*)(H + (size_t)c0 * C1 + lane * 4);
        const uint2 u1 = *(const uint2*)(H + (size_t)c1 * C1 + lane * 4);
        const uint2 u2 = *(const uint2*)(H + (size_t)c2 * C1 + lane * 4);
        const uint2 u3 = *(const uint2*)(H + (size_t)c3 * C1 + lane * 4);
        float2 f;
        f = __half22float2(*(const __half2*)&u0.x); a0 += f.x; a1 += f.y;
        f = __half22float2(*(const __half2*)&u0.y); a2 += f.x; a3 += f.y;
        f = __half22float2(*(const __half2*)&u1.x); a0 += f.x; a1 += f.y;
        f = __half22float2(*(const __half2*)&u1.y); a2 += f.x; a3 += f.y;
        f = __half22float2(*(const __half2*)&u2.x); a0 += f.x; a1 += f.y;
        f = __half22float2(*(const __half2*)&u2.y); a2 += f.x; a3 += f.y;
        f = __half22float2(*(const __half2*)&u3.x); a0 += f.x; a1 += f.y;
        f = __half22float2(*(const __half2*)&u3.y); a2 += f.x; a3 += f.y;
    }
    for (; j < e; ++j) {
        const int c0 = __ldg(cols + j);
        const uint2 u0 = *(const uint2*)(H + (size_t)c0 * C1 + lane * 4);
        float2 f;
        f = __half22float2(*(const __half2*)&u0.x); a0 += f.x; a1 += f.y;
        f = __half22float2(*(const __half2*)&u0.y); a2 += f.x; a3 += f.y;
    }
    const float d = __ldg(deg + row);
    const float4 bb = ((const float4*)b)[lane];
    __half2 o0 = __floats2half2_rn(fmaxf(fmaf(a0, d, bb.x), 0.f),
                                   fmaxf(fmaf(a1, d, bb.y), 0.f));
    __half2 o1 = __floats2half2_rn(fmaxf(fmaf(a2, d, bb.z), 0.f),
                                   fmaxf(fmaf(a3, d, bb.w), 0.f));
    uint2 u;
    u.x = *(unsigned*)&o0; u.y = *(unsigned*)&o1;
    *(uint2*)(x2 + (size_t)row * C1 + lane * 4) = u;
}

// ===========================================================================
// Gather 2: out[row,:] = (sum_{col_j<owned} h2[col_j,:]) * deg[row] + b2
// warp/row, 4-edge unroll, half2 per lane
// ===========================================================================
__global__ __launch_bounds__(256) void gather_out(
    const __half* __restrict__ H, const int* __restrict__ rs,
    const int* __restrict__ cols, const float* __restrict__ deg,
    const float* __restrict__ b, float* __restrict__ out, int owned)
{
    const int row  = (blockIdx.x * 256 + threadIdx.x) >> 5;
    const int lane = threadIdx.x & 31;
    if (row >= owned) return;
    const int s = __ldg(rs + row);
    const int e = __ldg(rs + row + 1);

    float a0 = 0.f, a1 = 0.f, b0 = 0.f, b1 = 0.f;
    int j = s;
    for (; j + 3 < e; j += 4) {
        int c0 = __ldg(cols + j),     c1 = __ldg(cols + j + 1);
        int c2 = __ldg(cols + j + 2), c3 = __ldg(cols + j + 3);
        if (c0 < owned) {
            float2 f = __half22float2(*(const __half2*)(H + (size_t)c0 * C2 + lane * 2));
            a0 += f.x; a1 += f.y;
        }
        if (c1 < owned) {
            float2 f = __half22float2(*(const __half2*)(H + (size_t)c1 * C2 + lane * 2));
            b0 += f.x; b1 += f.y;
        }
        if (c2 < owned) {
            float2 f = __half22float2(*(const __half2*)(H + (size_t)c2 * C2 + lane * 2));
            a0 += f.x; a1 += f.y;
        }
        if (c3 < owned) {
            float2 f = __half22float2(*(const __half2*)(H + (size_t)c3 * C2 + lane * 2));
            b0 += f.x; b1 += f.y;
        }
    }
    for (; j < e; ++j) {
        const int c0 = __ldg(cols + j);
        if (c0 < owned) {
            float2 f = __half22float2(*(const __half2*)(H + (size_t)c0 * C2 + lane * 2));
            a0 += f.x; a1 += f.y;
        }
    }
    const float d = __ldg(deg + row);
    const float2 bb = ((const float2*)b)[lane];
    float2 o;
    o.x = fmaf(a0 + b0, d, bb.x);
    o.y = fmaf(a1 + b1, d, bb.y);
    *(float2*)(out + (size_t)row * C2 + lane * 2) = o;
}

// ===========================================================================
extern "C" void kernel_launch(void* const* d_in, const int* in_sizes, int n_in,
                              void* d_out, int out_size)
{
    const float* x   = (const float*)d_in[0];
    const float* deg = (const float*)d_in[1];
    const float* w1  = (const float*)d_in[2];
    const float* b1  = (const float*)d_in[3];
    const float* w2  = (const float*)d_in[4];
    const float* b2  = (const float*)d_in[5];
    const int*   er  = (const int*)d_in[6];
    const int*   ec  = (const int*)d_in[7];

    const int nloc  = in_sizes[0] / C1;     // 55000
    const int nE    = in_sizes[6];          // 800000
    const int owned = out_size / C2;        // 50000
    float* out = (float*)d_out;

    __half *p_xh, *p_h, *p_x2, *p_h2;
    int *p_rs, *p_cur, *p_col, *p_meta;
    cudaGetSymbolAddress((void**)&p_xh,   g_xh);
    cudaGetSymbolAddress((void**)&p_h,    g_h);
    cudaGetSymbolAddress((void**)&p_x2,   g_x2);
    cudaGetSymbolAddress((void**)&p_h2,   g_h2);
    cudaGetSymbolAddress((void**)&p_rs,   g_rowstart);
    cudaGetSymbolAddress((void**)&p_cur,  g_cursor);
    cudaGetSymbolAddress((void**)&p_col,  g_csrcol);
    cudaGetSymbolAddress((void**)&p_meta, g_meta);

    int* p_hist  = p_meta;
    int* p_flags = p_meta + MAX_LOCAL;
    int* p_agg   = p_meta + MAX_LOCAL + 64;
    int* p_pfx   = p_meta + MAX_LOCAL + 128;

    // one-time side stream + events (resource init only; work is identical
    // and deterministic on every call)
    static cudaStream_t s2 = nullptr;
    static cudaEvent_t evFork = nullptr, evJoin = nullptr;
    if (s2 == nullptr) {
        cudaStreamCreateWithFlags(&s2, cudaStreamNonBlocking);
        cudaEventCreateWithFlags(&evFork, cudaEventDisableTiming);
        cudaEventCreateWithFlags(&evJoin, cudaEventDisableTiming);
    }

    // ---- fork: CSR build on s2, concurrent with convert+gemm1 on stream 0 ----
    cudaEventRecord(evFork, 0);
    cudaStreamWaitEvent(s2, evFork, 0);

    cudaMemsetAsync(p_meta, 0, (size_t)(MAX_LOCAL + 64) * sizeof(int), s2);
    edge_hist<<<(nE + 255) / 256, 256, 0, s2>>>(er, p_hist, nE);
    const int nB = (nloc + 1023) / 1024;
    scan_csr<<<nB, 1024, 0, s2>>>(p_hist, p_rs, p_cur, p_flags, p_agg, p_pfx, nloc);
    csr_fill<<<(nE + 255) / 256, 256, 0, s2>>>(er, ec, p_cur, p_col, nE);
    cudaEventRecord(evJoin, s2);

    // stream 0: X -> fp16, then layer-1 GEMM
    conv_half<<<(nloc * C1 / 8 + 255) / 256, 256>>>(x, p_xh, nloc * C1 / 8);
    {
        dim3 g((nloc + 127) / 128, C1 / 64);
        gemm_f16<<<g, 256>>>(p_xh, w1, deg, p_h, nloc, C1);
    }

    // ---- join, then gather1 (needs CSR + h) ----
    cudaStreamWaitEvent(0, evJoin, 0);
    gather_relu<<<(owned * 32 + 255) / 256, 256>>>(p_h, p_rs, p_col, deg, b1, p_x2, owned);

    // ---- layer 2 ----
    {
        dim3 g((owned + 127) / 128, 1);
        gemm_f16<<<g, 256>>>(p_x2, w2, deg, p_h2, owned, C2);
    }
    gather_out<<<(owned * 32 + 255) / 256, 256>>>(p_h2, p_rs, p_col, deg, b2, out, owned);
}